// round 16
// baseline (speedup 1.0000x reference)
#include <cuda_runtime.h>
#include <cstdint>

#define N_NODES 50000
#define EDGES   800000
#define NODE_NF 128
#define EDGE_NF 64
#define IN_NF   192
#define H_NF    256
#define OUT_NF  128

#define ROWS_CTA 64     // nodes per MLP CTA (1024 threads, 32 warps)
#define XS_STRIDE 196   // tf32 words per X row (192 + 4 pad)
#define HS_STRIDE 260   // tf32 words per H row (256 + 4 pad)
#define SMEM_TOTAL (ROWS_CTA * HS_STRIDE * 4)   // 66560 B

// Device scratch (alloc-free rule: __device__ globals).
__device__ float    g_agg[(size_t)N_NODES * EDGE_NF];
__device__ uint32_t g_W1p[IN_NF * H_NF];    // frag-packed tf32 W1 (N-block 32)
__device__ uint32_t g_W2p[H_NF * OUT_NF];   // frag-packed tf32 W2 (N-block 16)

__device__ __forceinline__ uint32_t f2tf(float f) {
    uint32_t u;
    asm("cvt.rna.tf32.f32 %0, %1;" : "=r"(u) : "f"(f));
    return u;
}

__device__ __forceinline__ void mma8(float* c, const uint32_t* a, const uint32_t* b) {
    asm volatile(
        "mma.sync.aligned.m16n8k8.row.col.f32.tf32.tf32.f32 "
        "{%0,%1,%2,%3}, {%4,%5,%6,%7}, {%8,%9}, {%0,%1,%2,%3};"
        : "+f"(c[0]), "+f"(c[1]), "+f"(c[2]), "+f"(c[3])
        : "r"(a[0]), "r"(a[1]), "r"(a[2]), "r"(a[3]), "r"(b[0]), "r"(b[1]));
}

// ---------------------------------------------------------------------------
// Weight pack kernels (canonical [K][N] f32 -> frag-ordered tf32).
// W1: g_W1p[(((ks*8+nb)*32+l)*8) + j*2+h] = tf32(W1[(ks*8+tg+h*4)*H_NF + nb*32 + g + j*8])
//   ks in [0,24), nb in [0,8), j in [0,4), h in {0,1}, g=l>>2, tg=l&3
// ---------------------------------------------------------------------------
__global__ void pack_w1_kernel(const float* __restrict__ W1) {
    int i = blockIdx.x * blockDim.x + threadIdx.x;
    if (i >= IN_NF * H_NF) return;
    int r = i & 7, l = (i >> 3) & 31, blk = i >> 8;   // blk = ks*8+nb
    int ks = blk >> 3, nb = blk & 7;
    int g = l >> 2, tg = l & 3, j = r >> 1, h = r & 1;
    int k = ks * 8 + tg + h * 4;
    int col = nb * 32 + g + j * 8;
    g_W1p[i] = f2tf(__ldg(W1 + (size_t)k * H_NF + col));
}

// W2: g_W2p[(((ks*8+nb)*32+l)*4) + j*2+h] = tf32(W2[(ks*8+tg+h*4)*OUT_NF + nb*16 + g + j*8])
//   ks in [0,32), nb in [0,8), j in [0,2), h in {0,1}
__global__ void pack_w2_kernel(const float* __restrict__ W2) {
    int i = blockIdx.x * blockDim.x + threadIdx.x;
    if (i >= H_NF * OUT_NF) return;
    int r = i & 3, l = (i >> 2) & 31, blk = i >> 7;   // blk = ks*8+nb
    int ks = blk >> 3, nb = blk & 7;
    int g = l >> 2, tg = l & 3, j = r >> 1, h = r & 1;
    int k = ks * 8 + tg + h * 4;
    int col = nb * 16 + g + j * 8;
    g_W2p[i] = f2tf(__ldg(W2 + (size_t)k * OUT_NF + col));
}

// ---------------------------------------------------------------------------
// Scatter-add with vector reduction (one red.global.add.v4.f32 per thread).
// ---------------------------------------------------------------------------
__global__ void scatter_kernel(const int* __restrict__ edge_index,
                               const float* __restrict__ edge_attr) {
    int idx = blockIdx.x * blockDim.x + threadIdx.x;
    if (idx >= EDGES * (EDGE_NF / 4)) return;
    int e = idx >> 4;
    int c = (idx & 15) << 2;
    int row = __ldg(edge_index + e);
    if ((unsigned)row >= (unsigned)N_NODES) return;
    float4 v = *reinterpret_cast<const float4*>(edge_attr + (size_t)e * EDGE_NF + c);
    float* dst = g_agg + (size_t)row * EDGE_NF + c;
    asm volatile("red.global.add.v4.f32 [%0], {%1,%2,%3,%4};"
                 :: "l"(dst), "f"(v.x), "f"(v.y), "f"(v.z), "f"(v.w)
                 : "memory");
}

// ---------------------------------------------------------------------------
// Fused MLP via tf32 mma.sync. 1024 threads = 32 warps (4 M-blocks x 8
// N-blocks), 64 nodes/CTA. Small warp tiles (16x32 / 16x16) cut accumulator
// registers so 32 warps fit per SM -> 2x latency hiding vs 16-warp config.
// ---------------------------------------------------------------------------
__global__ __launch_bounds__(1024, 1)
void mlp_mma_kernel(const float* __restrict__ node_feats,
                    const float* __restrict__ b1,
                    const float* __restrict__ b2,
                    float* __restrict__ out) {
    extern __shared__ uint32_t sm_u[];
    const int tid = threadIdx.x;
    const int node0 = blockIdx.x * ROWS_CTA;

    // ---- Stage X (node_feats | agg) -> smem, rounded to tf32 ----
    for (int i = tid; i < ROWS_CTA * 48; i += 1024) {
        int row = i / 48;
        int q = i % 48;
        int node = node0 + row;
        float4 v = make_float4(0.f, 0.f, 0.f, 0.f);
        if (node < N_NODES) {
            v = (q < 32)
                ? __ldg(reinterpret_cast<const float4*>(node_feats + (size_t)node * NODE_NF) + q)
                : __ldg(reinterpret_cast<const float4*>(g_agg + (size_t)node * EDGE_NF) + (q - 32));
        }
        uint32_t* dst = sm_u + row * XS_STRIDE + q * 4;
        dst[0] = f2tf(v.x); dst[1] = f2tf(v.y);
        dst[2] = f2tf(v.z); dst[3] = f2tf(v.w);
    }
    __syncthreads();

    const int w = tid >> 5, lane = tid & 31;
    const int g = lane >> 2, tg = lane & 3;
    const int wm = (w & 3) * 16;         // M block (0,16,32,48)
    const int nb = w >> 2;               // N block id (0..7)
    const int wn1 = nb * 32;             // GEMM1 N offset
    const int wn2 = nb * 16;             // GEMM2 N offset

    // ================= GEMM1: acc = X @ W1 (warp tile 16x32) =================
    float acc[4][4];
    #pragma unroll
    for (int j = 0; j < 4; j++)
        #pragma unroll
        for (int c = 0; c < 4; c++) acc[j][c] = 0.f;

    #pragma unroll 2
    for (int ks = 0; ks < IN_NF / 8; ks++) {
        const uint32_t* xr = sm_u + (wm + g) * XS_STRIDE + ks * 8 + tg;
        uint32_t af[4];
        af[0] = xr[0];
        af[1] = xr[8 * XS_STRIDE];
        af[2] = xr[4];
        af[3] = xr[8 * XS_STRIDE + 4];
        const uint4* bp = reinterpret_cast<const uint4*>(g_W1p)
                        + ((((ks * 8 + nb) * 32) + lane) << 1);
        uint4 q0 = __ldg(bp + 0), q1 = __ldg(bp + 1);
        uint32_t bw[8] = {q0.x, q0.y, q0.z, q0.w, q1.x, q1.y, q1.z, q1.w};
        #pragma unroll
        for (int j = 0; j < 4; j++)
            mma8(acc[j], af, &bw[j * 2]);
    }
    __syncthreads();   // all Xs reads done before Hs overwrites the union

    // ---- Epilogue 1: bias + relu -> Hs (tf32) ----
    {
        const int row = wm + g;
        #pragma unroll
        for (int j = 0; j < 4; j++) {
            const int col = wn1 + j * 8 + 2 * tg;
            float bb0 = __ldg(b1 + col), bb1 = __ldg(b1 + col + 1);
            sm_u[row * HS_STRIDE + col]           = f2tf(fmaxf(acc[j][0] + bb0, 0.f));
            sm_u[row * HS_STRIDE + col + 1]       = f2tf(fmaxf(acc[j][1] + bb1, 0.f));
            sm_u[(row + 8) * HS_STRIDE + col]     = f2tf(fmaxf(acc[j][2] + bb0, 0.f));
            sm_u[(row + 8) * HS_STRIDE + col + 1] = f2tf(fmaxf(acc[j][3] + bb1, 0.f));
        }
    }
    __syncthreads();

    // ================= GEMM2: acc2 = relu(H) @ W2 (warp tile 16x16) =========
    float acc2[2][4];
    #pragma unroll
    for (int j = 0; j < 2; j++)
        #pragma unroll
        for (int c = 0; c < 4; c++) acc2[j][c] = 0.f;

    #pragma unroll 2
    for (int ks = 0; ks < H_NF / 8; ks++) {
        const uint32_t* hr = sm_u + (wm + g) * HS_STRIDE + ks * 8 + tg;
        uint32_t af[4];
        af[0] = hr[0];
        af[1] = hr[8 * HS_STRIDE];
        af[2] = hr[4];
        af[3] = hr[8 * HS_STRIDE + 4];
        const uint4* bp = reinterpret_cast<const uint4*>(g_W2p)
                        + (((ks * 8 + nb) * 32) + lane);
        uint4 q0 = __ldg(bp);
        uint32_t bw[4] = {q0.x, q0.y, q0.z, q0.w};
        #pragma unroll
        for (int j = 0; j < 2; j++)
            mma8(acc2[j], af, &bw[j * 2]);
    }

    // ---- Epilogue 2: bias -> gmem ----
    {
        const int nodeA = node0 + wm + g;
        const int nodeB = nodeA + 8;
        #pragma unroll
        for (int j = 0; j < 2; j++) {
            const int col = wn2 + j * 8 + 2 * tg;
            float bb0 = __ldg(b2 + col), bb1 = __ldg(b2 + col + 1);
            if (nodeA < N_NODES) {
                out[(size_t)nodeA * OUT_NF + col]     = acc2[j][0] + bb0;
                out[(size_t)nodeA * OUT_NF + col + 1] = acc2[j][1] + bb1;
            }
            if (nodeB < N_NODES) {
                out[(size_t)nodeB * OUT_NF + col]     = acc2[j][2] + bb0;
                out[(size_t)nodeB * OUT_NF + col + 1] = acc2[j][3] + bb1;
            }
        }
    }
}

// ---------------------------------------------------------------------------
extern "C" void kernel_launch(void* const* d_in, const int* in_sizes, int n_in,
                              void* d_out, int out_size) {
    const float* node_feats = (const float*)d_in[0];
    const int*   edge_index = (const int*)d_in[1];
    const float* edge_attr  = (const float*)d_in[2];
    const float* W1         = (const float*)d_in[3];
    const float* b1         = (const float*)d_in[4];
    const float* W2         = (const float*)d_in[5];
    const float* b2         = (const float*)d_in[6];
    float*       out        = (float*)d_out;

    // 1) zero aggregates via async memset
    void* agg_ptr = nullptr;
    cudaGetSymbolAddress(&agg_ptr, g_agg);
    cudaMemsetAsync(agg_ptr, 0, (size_t)N_NODES * EDGE_NF * sizeof(float));

    // 2) pack weights to frag-ordered tf32
    pack_w1_kernel<<<(IN_NF * H_NF + 255) / 256, 256>>>(W1);
    pack_w2_kernel<<<(H_NF * OUT_NF + 255) / 256, 256>>>(W2);

    // 3) scatter-add edges (vector reductions)
    {
        int total = EDGES * (EDGE_NF / 4);
        scatter_kernel<<<(total + 255) / 256, 256>>>(edge_index, edge_attr);
    }

    // 4) fused MLP
    {
        cudaFuncSetAttribute(mlp_mma_kernel,
                             cudaFuncAttributeMaxDynamicSharedMemorySize, SMEM_TOTAL);
        int blocks = (N_NODES + ROWS_CTA - 1) / ROWS_CTA;   // 782
        mlp_mma_kernel<<<blocks, 1024, SMEM_TOTAL>>>(node_feats, b1, b2, out);
    }
}